// round 10
// baseline (speedup 1.0000x reference)
#include <cuda_runtime.h>
#include <cuda_fp16.h>

#define Bn   64
#define Cn   122
#define Tn   500
#define COn  64
#define Dn   128
#define Hn   8
#define FFn  256
#define Lln  2
#define BC   (Bn*Cn)        /* 7808 = 1952*4 */
#define EPSf 1e-5f

typedef unsigned long long ull;
typedef unsigned int uint32;

/* ---------------- scratch (device globals; no allocation) ---------------- */
__device__ float g_tok[BC*Dn];
__device__ float g_qkv[BC*3*Dn];
__device__ float g_ctx[BC*Dn];
__device__ float g_ff [BC*FFn];

/* fast erf-GELU: Abramowitz-Stegun 7.1.26, |erf err| <= 1.5e-7 */
__device__ __forceinline__ float gelu_f(float x){
    float z  = fabsf(x) * 0.70710678118654752440f;
    float t  = __fdividef(1.0f, 1.0f + 0.3275911f*z);
    float poly = t*(0.254829592f + t*(-0.284496736f +
                 t*(1.421413741f + t*(-1.453152027f + t*1.061405429f))));
    float erfz = 1.0f - poly*__expf(-z*z);
    float s = copysignf(erfz, x);
    return 0.5f*x*(1.0f + s);
}

/* packed f32x2 helpers (transformer GEMMs) */
__device__ __forceinline__ ull pk(float a, float b){
    ull r; asm("mov.b64 %0, {%1, %2};" : "=l"(r) : "f"(a), "f"(b)); return r;
}
__device__ __forceinline__ void fma2(ull& d, ull a, ull b){
    asm("fma.rn.f32x2 %0, %1, %2, %0;" : "+l"(d) : "l"(a), "l"(b));
}
__device__ __forceinline__ float2 upk(ull a){
    float2 f; asm("mov.b64 {%0, %1}, %2;" : "=f"(f.x), "=f"(f.y) : "l"(a)); return f;
}

/* fp16 mma m16n8k16, fp32 accum */
__device__ __forceinline__ void mma_f16(float* c,
    uint32 a0, uint32 a1, uint32 a2, uint32 a3, uint32 b0, uint32 b1){
    asm volatile("mma.sync.aligned.m16n8k16.row.col.f32.f16.f16.f32 "
        "{%0,%1,%2,%3}, {%4,%5,%6,%7}, {%8,%9}, {%0,%1,%2,%3};"
        : "+f"(c[0]), "+f"(c[1]), "+f"(c[2]), "+f"(c[3])
        : "r"(a0), "r"(a1), "r"(a2), "r"(a3), "r"(b0), "r"(b1));
}

__device__ __forceinline__ uint32 h2pack(__half lo, __half hi){
    __half2 h = __halves2half2(lo, hi);
    return *(uint32*)&h;
}

/* conv1 + BN + GELU + maxpool(2) -> actH/actL (fp16 split) */
__device__ __forceinline__ void conv1_run(
    int i0, int stride, const float* __restrict__ sx,
    const float* __restrict__ sw1,
    const float* __restrict__ sA1, const float* __restrict__ sB1,
    uint32* __restrict__ actH, uint32* __restrict__ actL)
{
    for (int i = i0; i < COn*250; i += stride) {
        int co = i / 250; int tp = i - co*250;
        const float* wp = &sw1[co*9];
        const float* xp = &sx[2*tp];
        float a0 = 0.f, a1 = 0.f;
        #pragma unroll
        for (int k = 0; k < 9; k++) { a0 += xp[k]*wp[k]; a1 += xp[k+1]*wp[k]; }
        float A = sA1[co], Bv = sB1[co];
        float y0 = gelu_f(a0*A + Bv);
        float y1 = gelu_f(a1*A + Bv);
        float m  = fmaxf(y0, y1);
        __half mh = __float2half_rn(m);
        __half ml = __float2half_rn(m - __half2float(mh));
        int hidx = ((co >> 1)*264 + 2 + tp)*2 + (co & 1);
        ((__half*)actH)[hidx] = mh;
        ((__half*)actL)[hidx] = ml;
    }
}

/* conv2 mma (3-term fp16) + BN/GELU/mean epilogue + proj.
   Run by the HIGH warp group (local t = 0..255).
   Internal sync via named barrier 1 (256 threads). */
__device__ __forceinline__ void mma_sample(
    const uint32* __restrict__ actH, const uint32* __restrict__ actL,
    const uint32* __restrict__ wH,   const uint32* __restrict__ wL,
    const float* __restrict__ sA2,   const float* __restrict__ sB2,
    float* __restrict__ spart, float* __restrict__ sh2,
    const float* __restrict__ pw, const float* __restrict__ pb,
    const float* __restrict__ emb, float* __restrict__ tok,
    int bc, int t)
{
    const int wid = t >> 5, lane = t & 31;
    const int mchunk = wid & 1, tchunk = wid >> 1;   /* 0..7 */
    const int g = lane >> 2, t4 = lane & 3;

    /* zero partial sums for this sample (buffer is reused) */
    if (t < 64) spart[t] = 0.f;
    asm volatile("bar.sync 1, 256;" ::: "memory");

    float acc[2][8][4];
    #pragma unroll
    for (int mi = 0; mi < 2; mi++)
        #pragma unroll
        for (int nj = 0; nj < 8; nj++)
            #pragma unroll
            for (int r = 0; r < 4; r++) acc[mi][nj][r] = 0.f;

    const int mrow0 = mchunk*32 + g;
    const int nbase = tchunk*64 + g;

    #pragma unroll 4
    for (int c16 = 0; c16 < 20; c16++) {
        const int kk = c16 >> 2;
        const int rb = ((c16 & 3)*8 + t4)*264;
        const int q0 = c16*8 + t4;
        uint32 aH[2][4], aL[2][4];
        #pragma unroll
        for (int mi = 0; mi < 2; mi++) {
            int r0 = (mrow0 + mi*16)*164 + q0;
            int r1 = r0 + 8*164;
            aH[mi][0] = wH[r0];     aH[mi][1] = wH[r1];
            aH[mi][2] = wH[r0 + 4]; aH[mi][3] = wH[r1 + 4];
            aL[mi][0] = wL[r0];     aL[mi][1] = wL[r1];
            aL[mi][2] = wL[r0 + 4]; aL[mi][3] = wL[r1 + 4];
        }
        #pragma unroll
        for (int nj = 0; nj < 8; nj++) {
            int cb = rb + nbase + nj*8 + kk;
            uint32 bh0 = actH[cb], bh1 = actH[cb + 4*264];
            uint32 bl0 = actL[cb], bl1 = actL[cb + 4*264];
            #pragma unroll
            for (int mi = 0; mi < 2; mi++) {
                mma_f16(acc[mi][nj], aH[mi][0], aH[mi][1], aH[mi][2], aH[mi][3], bh0, bh1);
                mma_f16(acc[mi][nj], aH[mi][0], aH[mi][1], aH[mi][2], aH[mi][3], bl0, bl1);
                mma_f16(acc[mi][nj], aL[mi][0], aL[mi][1], aL[mi][2], aL[mi][3], bh0, bh1);
            }
        }
    }

    /* epilogue: BN + GELU + partial mean over t */
    #pragma unroll
    for (int mi = 0; mi < 2; mi++) {
        #pragma unroll
        for (int h = 0; h < 2; h++) {
            int r = mchunk*32 + mi*16 + g + h*8;
            float A = sA2[r], Bv = sB2[r];
            float rs = 0.f;
            #pragma unroll
            for (int nj = 0; nj < 8; nj++) {
                #pragma unroll
                for (int p = 0; p < 2; p++) {
                    int col = tchunk*64 + nj*8 + 2*t4 + p;
                    if (col < 250)
                        rs += gelu_f(acc[mi][nj][h*2+p]*A + Bv);
                }
            }
            rs += __shfl_xor_sync(0xffffffffu, rs, 1);
            rs += __shfl_xor_sync(0xffffffffu, rs, 2);
            if (t4 == 0) atomicAdd(&spart[r], rs);
        }
    }
    asm volatile("bar.sync 1, 256;" ::: "memory");
    if (t < 64) sh2[t] = spart[t] * (1.f/250.f);
    asm volatile("bar.sync 1, 256;" ::: "memory");

    /* proj + elec_emb -> tok */
    if (t < 128) {
        const int d = t;
        float acc2 = pb[d];
        const float* pwr = &pw[d*COn];
        #pragma unroll 8
        for (int c = 0; c < 64; c++) acc2 += sh2[c]*__ldg(&pwr[c]);
        int cidx = bc % Cn;
        tok[bc*Dn + d] = acc2 + emb[cidx*Dn + d];
    }
}

/* ============================================================
   Kernel 1: fused conv pipeline, 512 threads, 4 samples/block.
   Warp-specialized 2-stage pipeline with HIGH warps (8-15) as the
   mma group (arbiter is hi-wid-first: mma never starves) and LOW
   warps (0-7) as the conv1 group:
     stage A   : all warps: loads + conv1(s0)
     stage i=0..3: HIGH: mma(s_i)+epi+proj | LOW: conv1(s_{i+1})
   Double-buffered act/sx/spart/sh2 (i&1).
   SMEM (bytes), total 227584:
     act0H @0  act0L @33792  act1H @67584  act1L @101376
     wH @135168 (41984)  wL @177152 (41984)
     sx0 @219136  sx1 @221184  sw1 @223232
     sA1/B1/A2/B2 @225536  spart0 @226560 spart1 @226816
     sh20 @227072  sh21 @227328
   ============================================================ */
__global__ void __launch_bounds__(512, 1) conv_kernel(
    const float* __restrict__ x,
    const float* __restrict__ w1, const float* __restrict__ cb1,
    const float* __restrict__ g1, const float* __restrict__ be1,
    const float* __restrict__ m1, const float* __restrict__ v1,
    const float* __restrict__ w2, const float* __restrict__ cb2,
    const float* __restrict__ g2, const float* __restrict__ be2,
    const float* __restrict__ m2, const float* __restrict__ v2,
    const float* __restrict__ pw, const float* __restrict__ pb,
    const float* __restrict__ emb, float* __restrict__ tok)
{
    extern __shared__ char smraw[];
    uint32* actH[2] = { (uint32*)(smraw),          (uint32*)(smraw + 67584) };
    uint32* actL[2] = { (uint32*)(smraw + 33792),  (uint32*)(smraw + 101376) };
    uint32* wH    = (uint32*)(smraw + 135168);
    uint32* wL    = (uint32*)(smraw + 177152);
    float* sxb[2] = { (float*)(smraw + 219136), (float*)(smraw + 221184) };
    float* sw1    = (float*)(smraw + 223232);
    float* sA1    = (float*)(smraw + 225536);
    float* sB1    = sA1 + 64;
    float* sA2    = sA1 + 128;
    float* sB2    = sA1 + 192;
    float* spartb[2] = { (float*)(smraw + 226560), (float*)(smraw + 226816) };
    float* sh2b[2]   = { (float*)(smraw + 227072), (float*)(smraw + 227328) };

    const int bc0 = blockIdx.x*4;
    const int tid = threadIdx.x;
    const int wid = tid >> 5;

    /* ---- stage A: all loads + conv1(s0) by all warps ---- */
    {
        int t = tid - 4;
        sxb[0][tid] = (t >= 0 && t < Tn) ? x[bc0*Tn + t] : 0.f;
    }
    for (int i = tid; i < COn*9; i += 512) sw1[i] = w1[i];
    if (tid < 64) {
        float a1 = g1[tid]*rsqrtf(v1[tid]+EPSf);
        sA1[tid] = a1;  sB1[tid] = (cb1[tid]-m1[tid])*a1 + be1[tid];
        float a2 = g2[tid]*rsqrtf(v2[tid]+EPSf);
        sA2[tid] = a2;  sB2[tid] = (cb2[tid]-m2[tid])*a2 + be2[tid];
    }
    /* weights hi+lo: pair (k=2q, k=2q+1) = (ci, ci+1), same kk */
    for (int i = tid; i < COn*160; i += 512) {
        int co = i / 160, q = i - co*160;
        int k0 = 2*q;
        int kk = k0 >> 6, ci = k0 & 63;
        float wa = w2[co*320 + ci*5 + kk];
        float wb = w2[co*320 + (ci+1)*5 + kk];
        __half wah = __float2half_rn(wa);
        __half wbh = __float2half_rn(wb);
        wH[co*164 + q] = h2pack(wah, wbh);
        wL[co*164 + q] = h2pack(__float2half_rn(wa - __half2float(wah)),
                                __float2half_rn(wb - __half2float(wbh)));
    }
    /* zero pad cols {0,1} U [252,264) in all act arrays */
    for (int i = tid; i < 32*14; i += 512) {
        int row = i / 14, j = i - row*14;
        int col = (j < 2) ? j : (250 + j);
        actH[0][row*264 + col] = 0u;  actL[0][row*264 + col] = 0u;
        actH[1][row*264 + col] = 0u;  actL[1][row*264 + col] = 0u;
    }
    __syncthreads();

    conv1_run(tid, 512, sxb[0], sw1, sA1, sB1, actH[0], actL[0]);

    /* ---- pipelined stages ---- */
    #pragma unroll
    for (int i = 0; i < 4; i++) {
        __syncthreads();
        int cur = i & 1, nxt = (i + 1) & 1;
        if (wid >= 8) {
            mma_sample(actH[cur], actL[cur], wH, wL, sA2, sB2,
                       spartb[cur], sh2b[cur],
                       pw, pb, emb, tok, bc0 + i, tid - 256);
        } else if (i + 1 < 4) {
            for (int li = tid; li < 512; li += 256) {
                int t = li - 4;
                sxb[nxt][li] = (t >= 0 && t < Tn) ? x[(bc0+i+1)*Tn + t] : 0.f;
            }
            asm volatile("bar.sync 2, 256;" ::: "memory");
            conv1_run(tid, 256, sxb[nxt], sw1, sA1, sB1, actH[nxt], actL[nxt]);
        }
    }
}

/* ============================================================
   Kernel 2: tiled GEMM  Y[M,N] = act(X[M,K] @ W[N,K]^T + bias)
   ============================================================ */
__global__ __launch_bounds__(256) void gemm_kernel(
    const float* __restrict__ X, const float* __restrict__ W,
    const float* __restrict__ bias, float* __restrict__ Y,
    int K, int N, int actGelu)
{
    extern __shared__ float sm[];
    float* sxT = sm;            /* [K][40] */
    float* swt = sm + K*40;     /* [K][65] */
    const int row0 = blockIdx.x*32;
    const int e0   = blockIdx.y*64;
    const int tid  = threadIdx.x;

    for (int li = tid; li < 32*K; li += 256) {
        int r = li / K, d = li - r*K;
        sxT[d*40 + r] = X[(row0+r)*K + d];
    }
    for (int li = tid; li < 64*K; li += 256) {
        int e = li / K, d = li - e*K;
        swt[d*65 + e] = W[(e0+e)*K + d];
    }
    __syncthreads();

    const int e_local = tid & 63, tg = tid >> 6;
    float bb = bias[e0 + e_local];
    ull acc[4];
    #pragma unroll
    for (int j = 0; j < 4; j++) acc[j] = pk(bb, bb);
    #pragma unroll 4
    for (int d = 0; d < K; d++) {
        ull Wp = pk(swt[d*65 + e_local], swt[d*65 + e_local]);
        const ull* tp = (const ull*)&sxT[d*40 + tg*8];
        fma2(acc[0], Wp, tp[0]);
        fma2(acc[1], Wp, tp[1]);
        fma2(acc[2], Wp, tp[2]);
        fma2(acc[3], Wp, tp[3]);
    }
    #pragma unroll
    for (int j = 0; j < 4; j++) {
        float2 y = upk(acc[j]);
        if (actGelu) { y.x = gelu_f(y.x); y.y = gelu_f(y.y); }
        Y[(row0 + tg*8 + 2*j  )*N + e0 + e_local] = y.x;
        Y[(row0 + tg*8 + 2*j+1)*N + e0 + e_local] = y.y;
    }
}

/* ============================================================
   Kernel 3: GEMM (N=128) + residual + LayerNorm epilogue
   ============================================================ */
__global__ __launch_bounds__(256) void gemm_ln_kernel(
    const float* __restrict__ X, const float* __restrict__ W,
    const float* __restrict__ bias,
    const float* __restrict__ Res,
    const float* __restrict__ lng, const float* __restrict__ lnb,
    float* __restrict__ Out, int K)
{
    extern __shared__ float sm[];
    float* sxT = sm;               /* [K][40]  */
    float* swt = sm + K*40;        /* [K][65]  */
    float* sy  = swt + K*65;       /* [32][132] */
    const int row0 = blockIdx.x*32;
    const int tid  = threadIdx.x;

    for (int li = tid; li < 32*K; li += 256) {
        int r = li / K, d = li - r*K;
        sxT[d*40 + r] = X[(row0+r)*K + d];
    }
    const int e_local = tid & 63, tg = tid >> 6;

    for (int e0 = 0; e0 < 128; e0 += 64) {
        __syncthreads();
        for (int li = tid; li < 64*K; li += 256) {
            int e = li / K, d = li - e*K;
            swt[d*65 + e] = W[(e0+e)*K + d];
        }
        __syncthreads();
        float bb = bias[e0 + e_local];
        ull acc[4];
        #pragma unroll
        for (int j = 0; j < 4; j++) acc[j] = pk(bb, bb);
        #pragma unroll 4
        for (int d = 0; d < K; d++) {
            ull Wp = pk(swt[d*65 + e_local], swt[d*65 + e_local]);
            const ull* tp = (const ull*)&sxT[d*40 + tg*8];
            fma2(acc[0], Wp, tp[0]);
            fma2(acc[1], Wp, tp[1]);
            fma2(acc[2], Wp, tp[2]);
            fma2(acc[3], Wp, tp[3]);
        }
        #pragma unroll
        for (int j = 0; j < 4; j++) {
            float2 y = upk(acc[j]);
            sy[(tg*8 + 2*j  )*132 + e0 + e_local] = y.x;
            sy[(tg*8 + 2*j+1)*132 + e0 + e_local] = y.y;
        }
    }
    __syncthreads();

    const int w = tid >> 5, lane = tid & 31;
    for (int q = 0; q < 4; q++) {
        int r = w*4 + q;
        float z[4]; float s1 = 0.f, s2 = 0.f;
        #pragma unroll
        for (int i = 0; i < 4; i++) {
            int idx = lane + 32*i;
            float zz = sy[r*132 + idx] + Res[(row0+r)*128 + idx];
            z[i] = zz; s1 += zz; s2 += zz*zz;
        }
        #pragma unroll
        for (int o = 16; o > 0; o >>= 1) {
            s1 += __shfl_xor_sync(0xffffffffu, s1, o);
            s2 += __shfl_xor_sync(0xffffffffu, s2, o);
        }
        float mean = s1*(1.f/128.f);
        float var  = s2*(1.f/128.f) - mean*mean;
        float rs   = rsqrtf(var + EPSf);
        #pragma unroll
        for (int i = 0; i < 4; i++) {
            int idx = lane + 32*i;
            Out[(row0+r)*128 + idx] = (z[i]-mean)*rs*lng[idx] + lnb[idx];
        }
    }
}

/* ============================================================
   Kernel 4: attention per (b, head). seq=122, dh=16.
   ============================================================ */
__global__ __launch_bounds__(128) void attn_kernel(
    const float* __restrict__ qkv, float* __restrict__ ctx)
{
    const int b = blockIdx.x >> 3, h = blockIdx.x & 7;
    extern __shared__ float sm[];
    float* sq = sm;                 /* [122][17] */
    float* sk = sm + 122*17;
    float* sv = sm + 2*122*17;
    float* sattb = sm + 3*122*17;   /* [4][128] */
    const int tid = threadIdx.x;

    for (int li = tid; li < 122*16; li += 128) {
        int s = li >> 4, d = li & 15;
        int base = (b*Cn + s)*384 + h*16 + d;
        sq[s*17 + d] = qkv[base];
        sk[s*17 + d] = qkv[base + 128];
        sv[s*17 + d] = qkv[base + 256];
    }
    __syncthreads();

    const int w = tid >> 5, lane = tid & 31;
    float* satt = sattb + w*128;

    for (int i = w; i < Cn; i += 4) {
        float sc[4];
        #pragma unroll
        for (int c = 0; c < 4; c++) {
            int kk = lane + 32*c;
            if (kk < Cn) {
                float s = 0.f;
                #pragma unroll
                for (int d = 0; d < 16; d++) s += sq[i*17 + d]*sk[kk*17 + d];
                sc[c] = s*0.25f;
            } else sc[c] = -1e30f;
        }
        float mx = fmaxf(fmaxf(sc[0], sc[1]), fmaxf(sc[2], sc[3]));
        #pragma unroll
        for (int o = 16; o > 0; o >>= 1) mx = fmaxf(mx, __shfl_xor_sync(0xffffffffu, mx, o));
        float p[4]; float sum = 0.f;
        #pragma unroll
        for (int c = 0; c < 4; c++) {
            int kk = lane + 32*c;
            p[c] = (kk < Cn) ? __expf(sc[c]-mx) : 0.f;
            sum += p[c];
        }
        #pragma unroll
        for (int o = 16; o > 0; o >>= 1) sum += __shfl_xor_sync(0xffffffffu, sum, o);
        float inv = __fdividef(1.f, sum);
        #pragma unroll
        for (int c = 0; c < 4; c++) {
            int kk = lane + 32*c;
            if (kk < Cn) satt[kk] = p[c]*inv;
        }
        __syncwarp();
        int d = lane & 15, half = lane >> 4;
        float a = 0.f;
        int j0 = half*61;
        for (int j = j0; j < j0 + 61; j++) a += satt[j]*sv[j*17 + d];
        a += __shfl_xor_sync(0xffffffffu, a, 16);
        if (lane < 16) ctx[(b*Cn + i)*Dn + h*16 + d] = a;
        __syncwarp();
    }
}

/* ============================================================
   Kernel 5: mean over C + per-subject head -> out[64,4]
   ============================================================ */
__global__ __launch_bounds__(128) void head_kernel(
    const float* __restrict__ tok, const int* __restrict__ sid,
    const float* __restrict__ hw, const float* __restrict__ hb,
    float* __restrict__ out)
{
    const int b = blockIdx.x;
    __shared__ float sp[128];
    const int d = threadIdx.x;
    float s = 0.f;
    for (int c = 0; c < Cn; c++) s += tok[(b*Cn + c)*Dn + d];
    sp[d] = s*(1.f/(float)Cn);
    __syncthreads();
    const int cls = threadIdx.x >> 5, lane = threadIdx.x & 31;
    const int sb = sid[b];
    float a = 0.f;
    #pragma unroll
    for (int i = 0; i < 4; i++) {
        int dd = lane + 32*i;
        a += sp[dd]*hw[(sb*4 + cls)*Dn + dd];
    }
    #pragma unroll
    for (int o = 16; o > 0; o >>= 1) a += __shfl_xor_sync(0xffffffffu, a, o);
    if (lane == 0) out[b*4 + cls] = a + hb[sb*4 + cls];
}

/* ============================================================ */
extern "C" void kernel_launch(void* const* d_in, const int* in_sizes, int n_in,
                              void* d_out, int out_size)
{
    const float* x       = (const float*)d_in[0];
    const int*   sid     = (const int*  )d_in[1];
    const float* conv1_w = (const float*)d_in[2];
    const float* conv1_b = (const float*)d_in[3];
    const float* bn1_g   = (const float*)d_in[4];
    const float* bn1_b   = (const float*)d_in[5];
    const float* bn1_m   = (const float*)d_in[6];
    const float* bn1_v   = (const float*)d_in[7];
    const float* conv2_w = (const float*)d_in[8];
    const float* conv2_b = (const float*)d_in[9];
    const float* bn2_g   = (const float*)d_in[10];
    const float* bn2_b   = (const float*)d_in[11];
    const float* bn2_m   = (const float*)d_in[12];
    const float* bn2_v   = (const float*)d_in[13];
    const float* proj_w  = (const float*)d_in[14];
    const float* proj_b  = (const float*)d_in[15];
    const float* emb     = (const float*)d_in[16];
    const float* qkv_w   = (const float*)d_in[17];
    const float* qkv_b   = (const float*)d_in[18];
    const float* out_w   = (const float*)d_in[19];
    const float* out_b   = (const float*)d_in[20];
    const float* ln1_g   = (const float*)d_in[21];
    const float* ln1_b   = (const float*)d_in[22];
    const float* ff1_w   = (const float*)d_in[23];
    const float* ff1_b   = (const float*)d_in[24];
    const float* ff2_w   = (const float*)d_in[25];
    const float* ff2_b   = (const float*)d_in[26];
    const float* ln2_g   = (const float*)d_in[27];
    const float* ln2_b   = (const float*)d_in[28];
    const float* heads_w = (const float*)d_in[29];
    const float* heads_b = (const float*)d_in[30];

    const int CONV_SMEM   = 227584;                        /* bytes */
    const int GEMM_SMEM   = (128*40 + 128*65)*4;           /* 53760 B  */
    const int GLN_SMEM128 = (128*40 + 128*65 + 32*132)*4;  /* 70656 B  */
    const int GLN_SMEM256 = (256*40 + 256*65 + 32*132)*4;  /* 124416 B */
    const int ATTN_SMEM   = (3*122*17 + 4*128)*4;          /* 26936 B  */

    cudaFuncSetAttribute(conv_kernel,    cudaFuncAttributeMaxDynamicSharedMemorySize, CONV_SMEM);
    cudaFuncSetAttribute(gemm_kernel,    cudaFuncAttributeMaxDynamicSharedMemorySize, GEMM_SMEM);
    cudaFuncSetAttribute(gemm_ln_kernel, cudaFuncAttributeMaxDynamicSharedMemorySize, GLN_SMEM256);

    float* tokp = nullptr; float* qkvp = nullptr; float* ctxp = nullptr; float* ffp = nullptr;
    cudaGetSymbolAddress((void**)&tokp, g_tok);
    cudaGetSymbolAddress((void**)&qkvp, g_qkv);
    cudaGetSymbolAddress((void**)&ctxp, g_ctx);
    cudaGetSymbolAddress((void**)&ffp,  g_ff);

    conv_kernel<<<BC/4, 512, CONV_SMEM>>>(
        x, conv1_w, conv1_b, bn1_g, bn1_b, bn1_m, bn1_v,
        conv2_w, conv2_b, bn2_g, bn2_b, bn2_m, bn2_v,
        proj_w, proj_b, emb, tokp);

    for (int l = 0; l < Lln; l++) {
        gemm_kernel<<<dim3(244, 6), 256, GEMM_SMEM>>>(
            tokp, qkv_w + l*3*Dn*Dn, qkv_b + l*3*Dn, qkvp, Dn, 3*Dn, 0);
        attn_kernel<<<Bn*Hn, 128, ATTN_SMEM>>>(qkvp, ctxp);
        gemm_ln_kernel<<<244, 256, GLN_SMEM128>>>(
            ctxp, out_w + l*Dn*Dn, out_b + l*Dn,
            tokp, ln1_g + l*Dn, ln1_b + l*Dn, tokp, Dn);
        gemm_kernel<<<dim3(244, 4), 256, GEMM_SMEM>>>(
            tokp, ff1_w + l*FFn*Dn, ff1_b + l*FFn, ffp, Dn, FFn, 1);
        gemm_ln_kernel<<<244, 256, GLN_SMEM256>>>(
            ffp, ff2_w + l*Dn*FFn, ff2_b + l*Dn,
            tokp, ln2_g + l*Dn, ln2_b + l*Dn, tokp, FFn);
    }

    head_kernel<<<Bn, 128>>>(tokp, sid, heads_w, heads_b, (float*)d_out);
}